// round 1
// baseline (speedup 1.0000x reference)
#include <cuda_runtime.h>
#include <cuda_bf16.h>
#include <cstdint>

#define S1 4097
#define SMAX 4096
#define DM 160
#define NH 4
#define HD 40
#define BATCH 4

// ---------------- device scratch (no allocation allowed) ----------------
__device__ float g_f[BATCH * S1 * DM];            // f after conv+pe  [b][s][c]
__device__ float g_q[BATCH * NH * S1 * HD];       // [b][h][s][d]
__device__ float g_k[BATCH * NH * S1 * HD];
__device__ float g_v[BATCH * NH * S1 * HD];
__device__ float g_att[BATCH * NH * S1 * HD];     // attention out (rows < 4096 used)
__device__ float g_stats[BATCH * SMAX * 2];       // mean, rstd per (b,s)

// ---------------- kernel 1: conv1(2x2,s2)+b1 -> conv2(1x1)+b2 -> leaky -> +pe -> f[b][s][c]
__global__ void k_conv(const float* __restrict__ x,
                       const float* __restrict__ w1, const float* __restrict__ b1,
                       const float* __restrict__ w2, const float* __restrict__ b2,
                       const float* __restrict__ pe)
{
    int j = blockIdx.x;      // 0..63
    int i = blockIdx.y;      // 0..63
    int b = blockIdx.z;      // 0..3
    int tid = threadIdx.x;   // 160 threads

    __shared__ __align__(16) float patch[256];   // [c0][ky*2+kx]
    __shared__ __align__(16) float out1[64];

    for (int t = tid; t < 256; t += 160) {
        int c0 = t >> 2, k = t & 3, ky = k >> 1, kx = k & 1;
        patch[t] = x[((b * 64 + c0) * 128 + (2 * i + ky)) * 128 + (2 * j + kx)];
    }
    __syncthreads();

    if (tid < 64) {
        const float4* p4 = (const float4*)patch;
        const float4* w4 = (const float4*)(w1 + tid * 256);
        float4 a = make_float4(0.f, 0.f, 0.f, 0.f);
        #pragma unroll
        for (int c0 = 0; c0 < 64; c0++) {
            float4 pv = p4[c0], wv = w4[c0];
            a.x += pv.x * wv.x; a.y += pv.y * wv.y;
            a.z += pv.z * wv.z; a.w += pv.w * wv.w;
        }
        out1[tid] = b1[tid] + a.x + a.y + a.z + a.w;
    }
    __syncthreads();

    // conv2 (1x1): 160 outputs
    const float4* o4 = (const float4*)out1;
    const float4* w24 = (const float4*)(w2 + tid * 64);
    float4 a = make_float4(0.f, 0.f, 0.f, 0.f);
    #pragma unroll
    for (int c1 = 0; c1 < 16; c1++) {
        float4 ov = o4[c1], wv = w24[c1];
        a.x += ov.x * wv.x; a.y += ov.y * wv.y;
        a.z += ov.z * wv.z; a.w += ov.w * wv.w;
    }
    float acc = b2[tid] + a.x + a.y + a.z + a.w;
    acc = (acc >= 0.f) ? acc : 0.01f * acc;
    int s = i * 64 + j;
    g_f[((size_t)b * S1 + s) * DM + tid] = acc + pe[s];
}

// ---------------- kernel 1b: pad row s=4096 (zeros + pe[4096])
__global__ void k_pad(const float* __restrict__ pe)
{
    int t = blockIdx.x * blockDim.x + threadIdx.x;
    if (t < BATCH * DM) {
        int b = t / DM, c = t % DM;
        g_f[((size_t)b * S1 + SMAX) * DM + c] = pe[SMAX];
    }
}

// ---------------- kernel 2: QKV projection  out[b][h][s][d] = sum_c f[b][s][c]*w[h*40+d][c]
__global__ void k_qkv(const float* __restrict__ wq, const float* __restrict__ wk,
                      const float* __restrict__ wv)
{
    __shared__ __align__(16) float fs[64 * DM];   // 40 KB
    const int NROWS = BATCH * S1;                 // 16388
    int row0 = blockIdx.x * 64;
    const float* w = (blockIdx.y == 0) ? wq : ((blockIdx.y == 1) ? wk : wv);
    float* outp = (blockIdx.y == 0) ? g_q : ((blockIdx.y == 1) ? g_k : g_v);
    int tid = threadIdx.x;   // 256

    for (int idx = tid; idx < 64 * DM / 4; idx += 256) {
        int gr = row0 + idx / (DM / 4);
        if (gr < NROWS)
            ((float4*)fs)[idx] = ((const float4*)g_f)[(size_t)row0 * (DM / 4) + idx];
    }
    __syncthreads();

    for (int idx = tid; idx < 64 * DM; idx += 256) {
        int m = idx / DM, n = idx % DM;
        int gr = row0 + m;
        if (gr >= NROWS) continue;
        const float4* fr = (const float4*)(fs + m * DM);
        const float4* wr = (const float4*)(w + n * DM);
        float4 a = make_float4(0.f, 0.f, 0.f, 0.f);
        #pragma unroll
        for (int k4 = 0; k4 < DM / 4; k4++) {
            float4 fv = fr[k4], wv = wr[k4];
            a.x += fv.x * wv.x; a.y += fv.y * wv.y;
            a.z += fv.z * wv.z; a.w += fv.w * wv.w;
        }
        float acc = a.x + a.y + a.z + a.w;
        int b = gr / S1, s = gr % S1;
        int h = n / HD, d = n % HD;
        outp[(((size_t)b * NH + h) * S1 + s) * HD + d] = acc;
    }
}

// ---------------- kernel 3: flash attention (fp32, one query row per thread)
__global__ void __launch_bounds__(128, 4) k_attn()
{
    int bh  = blockIdx.y;                       // 0..15
    int row = blockIdx.x * 128 + threadIdx.x;   // 0..4095
    const float* qb = g_q + (size_t)bh * S1 * HD;
    const float* kb = g_k + (size_t)bh * S1 * HD;
    const float* vb = g_v + (size_t)bh * S1 * HD;

    const float scale = 0.158113883f;   // 1/sqrt(40)
    float qr[HD];
    #pragma unroll
    for (int d = 0; d < HD; d++) qr[d] = qb[(size_t)row * HD + d] * scale;

    float mx = -1e30f, l = 0.f;
    float o[HD];
    #pragma unroll
    for (int d = 0; d < HD; d++) o[d] = 0.f;

    __shared__ __align__(16) float ks[32 * HD];
    __shared__ __align__(16) float vs[32 * HD];

    for (int n0 = 0; n0 < S1; n0 += 32) {
        int cnt = min(32, S1 - n0);
        __syncthreads();
        for (int idx = threadIdx.x; idx < cnt * HD; idx += 128) {
            ks[idx] = kb[(size_t)n0 * HD + idx];
            vs[idx] = vb[(size_t)n0 * HD + idx];
        }
        __syncthreads();
        for (int jj = 0; jj < cnt; jj++) {
            const float4* k4 = (const float4*)(ks + jj * HD);
            float s0 = 0.f, s1 = 0.f, s2 = 0.f, s3 = 0.f;
            #pragma unroll
            for (int t = 0; t < HD / 4; t++) {
                float4 kv = k4[t];
                s0 += qr[4 * t + 0] * kv.x;
                s1 += qr[4 * t + 1] * kv.y;
                s2 += qr[4 * t + 2] * kv.z;
                s3 += qr[4 * t + 3] * kv.w;
            }
            float s = (s0 + s1) + (s2 + s3);
            if (s > mx) {
                float corr = __expf(mx - s);
                l *= corr;
                #pragma unroll
                for (int d = 0; d < HD; d++) o[d] *= corr;
                mx = s;
            }
            float p = __expf(s - mx);
            l += p;
            const float4* v4 = (const float4*)(vs + jj * HD);
            #pragma unroll
            for (int t = 0; t < HD / 4; t++) {
                float4 vv = v4[t];
                o[4 * t + 0] += p * vv.x;
                o[4 * t + 1] += p * vv.y;
                o[4 * t + 2] += p * vv.z;
                o[4 * t + 3] += p * vv.w;
            }
        }
    }
    float inv = 1.f / l;
    float* ob = g_att + (size_t)bh * S1 * HD + (size_t)row * HD;
    #pragma unroll
    for (int d = 0; d < HD; d++) ob[d] = o[d] * inv;
}

// ---------------- kernel 4: per-(b,s) LN stats over 160 channels
__global__ void k_stats()
{
    int r = blockIdx.x;            // 0..16383
    int b = r >> 12, s = r & 4095;
    int tid = threadIdx.x;         // 256
    float v = 0.f;
    if (tid < DM) {
        int h = tid / HD, d = tid % HD;
        v = g_att[(((size_t)b * NH + h) * S1 + s) * HD + d];
    }
    __shared__ float r1[256], r2[256];
    r1[tid] = v; r2[tid] = v * v;
    __syncthreads();
    for (int off = 128; off > 0; off >>= 1) {
        if (tid < off) { r1[tid] += r1[tid + off]; r2[tid] += r2[tid + off]; }
        __syncthreads();
    }
    if (tid == 0) {
        float mean = r1[0] * (1.f / DM);
        float var  = r2[0] * (1.f / DM) - mean * mean;
        g_stats[2 * r]     = mean;
        g_stats[2 * r + 1] = rsqrtf(var + 1e-5f);
    }
}

// ---------------- kernel 5: LN + residual + 2x2 nearest upsample
__global__ void k_out(const float* __restrict__ ln_w, const float* __restrict__ ln_b,
                      float* __restrict__ out)
{
    int tx = threadIdx.x;          // 32 -> j
    int ty = threadIdx.y;          // 8  -> c sub
    int j = blockIdx.x * 32 + tx;  // 0..63
    int i = blockIdx.y;            // 0..63
    int bz = blockIdx.z;           // 0..79
    int b = bz / 20, cg = bz % 20;
    int c = cg * 8 + ty;           // 0..159
    int s = i * 64 + j;
    int h = c / HD, d = c % HD;

    float v = g_att[(((size_t)b * NH + h) * S1 + s) * HD + d];
    float mean = g_stats[2 * (b * SMAX + s)];
    float rstd = g_stats[2 * (b * SMAX + s) + 1];
    float ln = (v - mean) * rstd * ln_w[c] + ln_b[c];
    float ov = ln + v;

    size_t base = (((size_t)b * DM + c) * 128 + 2 * i) * 128 + 2 * j;
    float2 v2 = make_float2(ov, ov);
    *(float2*)(out + base)       = v2;
    *(float2*)(out + base + 128) = v2;
}

// ---------------- launch ----------------
extern "C" void kernel_launch(void* const* d_in, const int* in_sizes, int n_in,
                              void* d_out, int out_size)
{
    const float* x   = (const float*)d_in[0];
    const float* w1  = (const float*)d_in[1];
    const float* b1  = (const float*)d_in[2];
    const float* w2  = (const float*)d_in[3];
    const float* b2  = (const float*)d_in[4];
    const float* pe  = (const float*)d_in[5];
    const float* wq  = (const float*)d_in[6];
    const float* wk  = (const float*)d_in[7];
    const float* wv  = (const float*)d_in[8];
    const float* lnw = (const float*)d_in[9];
    const float* lnb = (const float*)d_in[10];
    float* out = (float*)d_out;

    k_conv<<<dim3(64, 64, BATCH), 160>>>(x, w1, b1, w2, b2, pe);
    k_pad<<<1, BATCH * DM>>>(pe);
    k_qkv<<<dim3((BATCH * S1 + 63) / 64, 3), 256>>>(wq, wk, wv);
    k_attn<<<dim3(SMAX / 128, BATCH * NH), 128>>>();
    k_stats<<<BATCH * SMAX, 256>>>();
    k_out<<<dim3(2, 64, BATCH * 20), dim3(32, 8)>>>(lnw, lnb, out);
}

// round 4
// speedup vs baseline: 2.6185x; 2.6185x over previous
#include <cuda_runtime.h>
#include <cuda_fp16.h>
#include <cuda_bf16.h>
#include <cstdint>

#define S1 4097
#define SMAX 4096
#define DM 160
#define NH 4
#define HD 40
#define BATCH 4
#define KT 64
#define NTK 65           // ceil(4097/64)
#define L2E 1.4426950408889634f

// ---------------- device scratch ----------------
__device__ float g_f[BATCH * S1 * DM];
__device__ float g_q[BATCH * NH * S1 * HD];
__device__ float g_k[BATCH * NH * S1 * HD];
__device__ float g_v[BATCH * NH * S1 * HD];
__device__ float g_att[BATCH * NH * S1 * HD];
__device__ float g_stats[BATCH * SMAX * 2];

// ---------------- mma helpers (legacy mma.sync — compiles on compute_103) ----
__device__ __forceinline__ void mma_tf32(float* c, const uint32_t* a, const uint32_t* b) {
    asm volatile(
        "mma.sync.aligned.m16n8k8.row.col.f32.tf32.tf32.f32 "
        "{%0,%1,%2,%3}, {%4,%5,%6,%7}, {%8,%9}, {%0,%1,%2,%3};"
        : "+f"(c[0]), "+f"(c[1]), "+f"(c[2]), "+f"(c[3])
        : "r"(a[0]), "r"(a[1]), "r"(a[2]), "r"(a[3]), "r"(b[0]), "r"(b[1]));
}
__device__ __forceinline__ void mma_f16(float* c, const uint32_t* a, const uint32_t* b) {
    asm volatile(
        "mma.sync.aligned.m16n8k16.row.col.f32.f16.f16.f32 "
        "{%0,%1,%2,%3}, {%4,%5,%6,%7}, {%8,%9}, {%0,%1,%2,%3};"
        : "+f"(c[0]), "+f"(c[1]), "+f"(c[2]), "+f"(c[3])
        : "r"(a[0]), "r"(a[1]), "r"(a[2]), "r"(a[3]), "r"(b[0]), "r"(b[1]));
}
__device__ __forceinline__ float to_tf32(float x) {
    float r;
    asm("cvt.rna.tf32.f32 %0, %1;" : "=f"(r) : "f"(x));
    return r;
}
__device__ __forceinline__ uint32_t pack_ex2_f16x2(float lo, float hi) {
    uint32_t p, r;
    asm("cvt.rn.f16x2.f32 %0, %1, %2;" : "=r"(p) : "f"(hi), "f"(lo));
    asm("ex2.approx.f16x2 %0, %1;" : "=r"(r) : "r"(p));
    return r;
}
__device__ __forceinline__ uint32_t pack_f16x2(float lo, float hi) {
    uint32_t p;
    asm("cvt.rn.f16x2.f32 %0, %1, %2;" : "=r"(p) : "f"(hi), "f"(lo));
    return p;
}

// ================= flash attention: tf32 QK mma + f16 PV mma =================
// CTA: 128 threads (4 warps). Each CTA: 128 query rows of one (b,h).
// Warp w: rows [w*32, w*32+32). KT=64 keys per iteration.
__global__ void __launch_bounds__(128) k_flash2()
{
    __shared__ float Qs[128 * 41];       // Q tile, stride 41 (tf32-rounded, scaled)
    __shared__ float Ks[64 * 41];        // K tile, stride 41 (tf32-rounded)
    __shared__ uint32_t Vs[32 * 56];     // V as half2 key-pairs: [pair][dim], stride 56
                                         // dim 40 = ones column (row-sum trick), 41..47 zero

    const int tid = threadIdx.x;
    const int w   = tid >> 5;
    const int lane = tid & 31;
    const int g   = lane >> 2;           // groupID (row within m8)
    const int tg  = lane & 3;            // thread-in-group (col pair)
    const int qt  = blockIdx.x;          // 0..31
    const int bh  = blockIdx.y;          // 0..15

    const float* qb = g_q + (size_t)bh * S1 * HD;
    const float* kb = g_k + (size_t)bh * S1 * HD;
    const float* vb = g_v + (size_t)bh * S1 * HD;

    // ---- load Q tile (scaled by 1/sqrt(40), tf32-rounded) ----
    for (int idx = tid; idx < 128 * HD; idx += 128) {
        int r = idx / HD, d = idx % HD;
        Qs[r * 41 + d] = to_tf32(qb[(size_t)(qt * 128 + r) * HD + d] * 0.158113883f);
    }
    // ---- zero V pad columns (41..55) once ----
    for (int idx = tid; idx < 32 * 56; idx += 128) Vs[idx] = 0u;

    float o[2][6][4];                    // O accum: 2 mtiles x 6 ntiles(48 dims incl l-col)
    #pragma unroll
    for (int a = 0; a < 2; a++)
        #pragma unroll
        for (int b = 0; b < 6; b++)
            #pragma unroll
            for (int c = 0; c < 4; c++) o[a][b][c] = 0.f;
    float m[4] = { -1e30f, -1e30f, -1e30f, -1e30f };   // row maxes: [mt*2 + half]

    for (int t = 0; t < NTK; t++) {
        __syncthreads();   // previous compute done before overwriting K/V
        // ---- load K tile ----
        for (int idx = tid; idx < KT * HD; idx += 128) {
            int r = idx / HD, d = idx % HD;
            int s = t * KT + r;
            float v = (s < S1) ? kb[(size_t)s * HD + d] : 0.f;
            Ks[r * 41 + d] = to_tf32(v);
        }
        // ---- load V tile as half2 key-pairs + ones column ----
        for (int idx = tid; idx < 32 * 41; idx += 128) {
            int p = idx / 41, d = idx % 41;
            uint32_t val;
            if (d == 40) {
                val = pack_f16x2(1.f, 1.f);
            } else {
                int k0 = t * KT + 2 * p;
                float v0 = (k0     < S1) ? vb[(size_t)k0 * HD + d]       : 0.f;
                float v1 = (k0 + 1 < S1) ? vb[(size_t)(k0 + 1) * HD + d] : 0.f;
                val = pack_f16x2(v0, v1);
            }
            Vs[p * 56 + d] = val;
        }
        __syncthreads();

        // ---- S = Q K^T (tf32 mma), s[mt][nt][4] ----
        float s[2][8][4];
        #pragma unroll
        for (int a = 0; a < 2; a++)
            #pragma unroll
            for (int b = 0; b < 8; b++)
                #pragma unroll
                for (int c = 0; c < 4; c++) s[a][b][c] = 0.f;

        #pragma unroll
        for (int kt = 0; kt < 5; kt++) {
            uint32_t bb[8][2];
            #pragma unroll
            for (int nt = 0; nt < 8; nt++) {
                bb[nt][0] = __float_as_uint(Ks[(g + 8 * nt) * 41 + tg + 8 * kt]);
                bb[nt][1] = __float_as_uint(Ks[(g + 8 * nt) * 41 + tg + 4 + 8 * kt]);
            }
            #pragma unroll
            for (int mt = 0; mt < 2; mt++) {
                int r0 = w * 32 + mt * 16 + g;
                uint32_t aa[4];
                aa[0] = __float_as_uint(Qs[r0 * 41 + tg + 8 * kt]);
                aa[1] = __float_as_uint(Qs[(r0 + 8) * 41 + tg + 8 * kt]);
                aa[2] = __float_as_uint(Qs[r0 * 41 + tg + 4 + 8 * kt]);
                aa[3] = __float_as_uint(Qs[(r0 + 8) * 41 + tg + 4 + 8 * kt]);
                #pragma unroll
                for (int nt = 0; nt < 8; nt++) mma_tf32(s[mt][nt], aa, bb[nt]);
            }
        }

        // ---- mask invalid keys (only last tile) ----
        if (t == NTK - 1) {
            #pragma unroll
            for (int nt = 0; nt < 8; nt++) {
                int base = t * KT + 8 * nt + 2 * tg;
                if (base >= S1) {
                    s[0][nt][0] = s[0][nt][2] = s[1][nt][0] = s[1][nt][2] = -1e30f;
                }
                if (base + 1 >= S1) {
                    s[0][nt][1] = s[0][nt][3] = s[1][nt][1] = s[1][nt][3] = -1e30f;
                }
            }
        }

        // ---- row max (local + quad shuffle) ----
        float mnew[4], corr[4], mL[4];
        #pragma unroll
        for (int r = 0; r < 4; r++) {
            int mt = r >> 1, hf = r & 1;
            float mx = -1e30f;
            #pragma unroll
            for (int nt = 0; nt < 8; nt++) {
                mx = fmaxf(mx, s[mt][nt][2 * hf]);
                mx = fmaxf(mx, s[mt][nt][2 * hf + 1]);
            }
            mx = fmaxf(mx, __shfl_xor_sync(0xFFFFFFFFu, mx, 1));
            mx = fmaxf(mx, __shfl_xor_sync(0xFFFFFFFFu, mx, 2));
            mnew[r] = fmaxf(m[r], mx);
            corr[r] = __expf(m[r] - mnew[r]);
            m[r] = mnew[r];
            mL[r] = m[r] * L2E;
        }

        // ---- rescale O ----
        #pragma unroll
        for (int mt = 0; mt < 2; mt++)
            #pragma unroll
            for (int nt = 0; nt < 6; nt++) {
                o[mt][nt][0] *= corr[mt * 2];
                o[mt][nt][1] *= corr[mt * 2];
                o[mt][nt][2] *= corr[mt * 2 + 1];
                o[mt][nt][3] *= corr[mt * 2 + 1];
            }

        // ---- P = exp(S - m) as f16x2 A-fragments ----
        uint32_t pf[2][8][2];
        #pragma unroll
        for (int mt = 0; mt < 2; mt++)
            #pragma unroll
            for (int nt = 0; nt < 8; nt++) {
                float f0 = __fmaf_rn(s[mt][nt][0], L2E, -mL[mt * 2]);
                float f1 = __fmaf_rn(s[mt][nt][1], L2E, -mL[mt * 2]);
                float f2 = __fmaf_rn(s[mt][nt][2], L2E, -mL[mt * 2 + 1]);
                float f3 = __fmaf_rn(s[mt][nt][3], L2E, -mL[mt * 2 + 1]);
                pf[mt][nt][0] = pack_ex2_f16x2(f0, f1);
                pf[mt][nt][1] = pack_ex2_f16x2(f2, f3);
            }

        // ---- O += P V (f16 mma, n covers 40 dims + l column) ----
        #pragma unroll
        for (int kt = 0; kt < 4; kt++) {
            uint32_t bb[6][2];
            #pragma unroll
            for (int nt = 0; nt < 6; nt++) {
                bb[nt][0] = Vs[(8 * kt + tg) * 56 + g + 8 * nt];
                bb[nt][1] = Vs[(8 * kt + tg + 4) * 56 + g + 8 * nt];
            }
            #pragma unroll
            for (int mt = 0; mt < 2; mt++) {
                uint32_t aa[4] = { pf[mt][2 * kt][0], pf[mt][2 * kt][1],
                                   pf[mt][2 * kt + 1][0], pf[mt][2 * kt + 1][1] };
                #pragma unroll
                for (int nt = 0; nt < 6; nt++) mma_f16(o[mt][nt], aa, bb[nt]);
            }
        }
    }

    // ---- epilogue: l from ones-column, normalize, store ----
    #pragma unroll
    for (int mt = 0; mt < 2; mt++) {
        float l0 = __shfl_sync(0xFFFFFFFFu, o[mt][5][0], lane & ~3);
        float l1 = __shfl_sync(0xFFFFFFFFu, o[mt][5][2], lane & ~3);
        float inv0 = 1.f / l0, inv1 = 1.f / l1;
        int row0 = qt * 128 + w * 32 + mt * 16 + g;
        float* ob0 = g_att + ((size_t)bh * S1 + row0) * HD;
        float* ob1 = g_att + ((size_t)bh * S1 + row0 + 8) * HD;
        #pragma unroll
        for (int nt = 0; nt < 5; nt++) {
            int d = 8 * nt + 2 * tg;
            *(float2*)(ob0 + d) = make_float2(o[mt][nt][0] * inv0, o[mt][nt][1] * inv0);
            *(float2*)(ob1 + d) = make_float2(o[mt][nt][2] * inv1, o[mt][nt][3] * inv1);
        }
    }
}

// ================= conv =================
__global__ void k_conv(const float* __restrict__ x,
                       const float* __restrict__ w1, const float* __restrict__ b1,
                       const float* __restrict__ w2, const float* __restrict__ b2,
                       const float* __restrict__ pe)
{
    int j = blockIdx.x, i = blockIdx.y, b = blockIdx.z;
    int tid = threadIdx.x;
    __shared__ __align__(16) float patch[256];
    __shared__ __align__(16) float out1[64];
    for (int t = tid; t < 256; t += 160) {
        int c0 = t >> 2, k = t & 3, ky = k >> 1, kx = k & 1;
        patch[t] = x[((b * 64 + c0) * 128 + (2 * i + ky)) * 128 + (2 * j + kx)];
    }
    __syncthreads();
    if (tid < 64) {
        const float4* p4 = (const float4*)patch;
        const float4* w4 = (const float4*)(w1 + tid * 256);
        float4 a = make_float4(0.f, 0.f, 0.f, 0.f);
        #pragma unroll
        for (int c0 = 0; c0 < 64; c0++) {
            float4 pv = p4[c0], wv = w4[c0];
            a.x += pv.x * wv.x; a.y += pv.y * wv.y;
            a.z += pv.z * wv.z; a.w += pv.w * wv.w;
        }
        out1[tid] = b1[tid] + a.x + a.y + a.z + a.w;
    }
    __syncthreads();
    const float4* o4 = (const float4*)out1;
    const float4* w24 = (const float4*)(w2 + tid * 64);
    float4 a = make_float4(0.f, 0.f, 0.f, 0.f);
    #pragma unroll
    for (int c1 = 0; c1 < 16; c1++) {
        float4 ov = o4[c1], wv = w24[c1];
        a.x += ov.x * wv.x; a.y += ov.y * wv.y;
        a.z += ov.z * wv.z; a.w += ov.w * wv.w;
    }
    float acc = b2[tid] + a.x + a.y + a.z + a.w;
    acc = (acc >= 0.f) ? acc : 0.01f * acc;
    int s = i * 64 + j;
    g_f[((size_t)b * S1 + s) * DM + tid] = acc + pe[s];
}

__global__ void k_pad(const float* __restrict__ pe)
{
    int t = blockIdx.x * blockDim.x + threadIdx.x;
    if (t < BATCH * DM) {
        int b = t / DM, c = t % DM;
        g_f[((size_t)b * S1 + SMAX) * DM + c] = pe[SMAX];
    }
}

// ================= QKV projection (smem-tiled GEMM) =================
// Block: 512 threads, 32 rows x 160 outputs. blockIdx.y selects q/k/v.
__global__ void __launch_bounds__(512) k_qkv(const float* __restrict__ wq,
                                             const float* __restrict__ wk,
                                             const float* __restrict__ wv)
{
    __shared__ float fsT[160 * 33];      // f transposed [k][m], padded
    __shared__ float wsT[40 * 161];      // w chunk transposed [kk][n], padded
    const int NROWS = BATCH * S1;
    int row0 = blockIdx.x * 32;
    const float* w = (blockIdx.y == 0) ? wq : ((blockIdx.y == 1) ? wk : wv);
    float* outp = (blockIdx.y == 0) ? g_q : ((blockIdx.y == 1) ? g_k : g_v);
    int tid = threadIdx.x;

    for (int idx = tid; idx < 32 * DM; idx += 512) {
        int mm = idx / DM, c = idx % DM;
        int gr = row0 + mm;
        fsT[c * 33 + mm] = (gr < NROWS) ? g_f[(size_t)gr * DM + c] : 0.f;
    }

    int tn = tid & 31;         // n-group (lane)
    int tm = tid >> 5;         // 0..15
    int n0 = tn * 5;
    int m0 = tm * 2;
    float acc[2][5] = {};

    for (int c4 = 0; c4 < 4; c4++) {
        __syncthreads();
        for (int idx = tid; idx < DM * 40; idx += 512) {
            int n = idx / 40, kk = idx % 40;
            wsT[kk * 161 + n] = w[n * DM + c4 * 40 + kk];
        }
        __syncthreads();
        #pragma unroll 4
        for (int kk = 0; kk < 40; kk++) {
            int k = c4 * 40 + kk;
            float f0 = fsT[k * 33 + m0];
            float f1 = fsT[k * 33 + m0 + 1];
            #pragma unroll
            for (int i = 0; i < 5; i++) {
                float wv_ = wsT[kk * 161 + n0 + i];
                acc[0][i] = __fmaf_rn(f0, wv_, acc[0][i]);
                acc[1][i] = __fmaf_rn(f1, wv_, acc[1][i]);
            }
        }
    }

    #pragma unroll
    for (int mi = 0; mi < 2; mi++) {
        int gr = row0 + m0 + mi;
        if (gr >= NROWS) continue;
        int b = gr / S1, s = gr % S1;
        #pragma unroll
        for (int i = 0; i < 5; i++) {
            int n = n0 + i;
            int h = n / HD, d = n % HD;
            outp[(((size_t)b * NH + h) * S1 + s) * HD + d] = acc[mi][i];
        }
    }
}

// ================= LN stats =================
__global__ void k_stats()
{
    int r = blockIdx.x;
    int b = r >> 12, s = r & 4095;
    int tid = threadIdx.x;
    float v = 0.f;
    if (tid < DM) {
        int h = tid / HD, d = tid % HD;
        v = g_att[(((size_t)b * NH + h) * S1 + s) * HD + d];
    }
    __shared__ float r1[256], r2[256];
    r1[tid] = v; r2[tid] = v * v;
    __syncthreads();
    for (int off = 128; off > 0; off >>= 1) {
        if (tid < off) { r1[tid] += r1[tid + off]; r2[tid] += r2[tid + off]; }
        __syncthreads();
    }
    if (tid == 0) {
        float mean = r1[0] * (1.f / DM);
        float var  = r2[0] * (1.f / DM) - mean * mean;
        g_stats[2 * r]     = mean;
        g_stats[2 * r + 1] = rsqrtf(var + 1e-5f);
    }
}

// ================= LN + residual + upsample =================
__global__ void k_out(const float* __restrict__ ln_w, const float* __restrict__ ln_b,
                      float* __restrict__ out)
{
    int tx = threadIdx.x, ty = threadIdx.y;
    int j = blockIdx.x * 32 + tx;
    int i = blockIdx.y;
    int bz = blockIdx.z;
    int b = bz / 20, cg = bz % 20;
    int c = cg * 8 + ty;
    int s = i * 64 + j;
    int h = c / HD, d = c % HD;
    float v = g_att[(((size_t)b * NH + h) * S1 + s) * HD + d];
    float mean = g_stats[2 * (b * SMAX + s)];
    float rstd = g_stats[2 * (b * SMAX + s) + 1];
    float ln = (v - mean) * rstd * ln_w[c] + ln_b[c];
    float ov = ln + v;
    size_t base = (((size_t)b * DM + c) * 128 + 2 * i) * 128 + 2 * j;
    float2 v2 = make_float2(ov, ov);
    *(float2*)(out + base)       = v2;
    *(float2*)(out + base + 128) = v2;
}

// ---------------- launch ----------------
extern "C" void kernel_launch(void* const* d_in, const int* in_sizes, int n_in,
                              void* d_out, int out_size)
{
    const float* x   = (const float*)d_in[0];
    const float* w1  = (const float*)d_in[1];
    const float* b1  = (const float*)d_in[2];
    const float* w2  = (const float*)d_in[3];
    const float* b2  = (const float*)d_in[4];
    const float* pe  = (const float*)d_in[5];
    const float* wq  = (const float*)d_in[6];
    const float* wk  = (const float*)d_in[7];
    const float* wv  = (const float*)d_in[8];
    const float* lnw = (const float*)d_in[9];
    const float* lnb = (const float*)d_in[10];
    float* out = (float*)d_out;

    k_conv<<<dim3(64, 64, BATCH), 160>>>(x, w1, b1, w2, b2, pe);
    k_pad<<<1, BATCH * DM>>>(pe);
    k_qkv<<<dim3((BATCH * S1 + 31) / 32, 3), 512>>>(wq, wk, wv);
    k_flash2<<<dim3(SMAX / 128, BATCH * NH), 128>>>();
    k_stats<<<BATCH * SMAX, 256>>>();
    k_out<<<dim3(2, 64, BATCH * 20), dim3(32, 8)>>>(lnw, lnb, out);
}